// round 1
// baseline (speedup 1.0000x reference)
#include <cuda_runtime.h>

// Problem constants (fixed by the dataset)
#define N_IN   200000
#define N_OUT  100000
#define NE     1600000
#define CIN    64
#define KK     9
#define CA     96
#define CB     32
#define CO     128          // CA + CB
#define KCDIM  576          // KK * CIN
#define MPTS   32           // output points per CTA

// Scratch (device globals: no allocations allowed)
__device__ int   g_offs[N_OUT + 1];
__device__ float g_W2[KCDIM * CO];

// ---------------------------------------------------------------------------
// Build CSR offsets from the SORTED neighbors_out_index via binary search.
// g_offs[n] = first edge e with out_idx[e] >= n ; g_offs[N_OUT] = NE.
// ---------------------------------------------------------------------------
__global__ void build_offsets_kernel(const int* __restrict__ out_idx) {
    int n = blockIdx.x * blockDim.x + threadIdx.x;
    if (n > N_OUT) return;
    int lo = 0, hi = NE;
    while (lo < hi) {
        int mid = (lo + hi) >> 1;
        if (__ldg(out_idx + mid) < n) lo = mid + 1; else hi = mid;
    }
    g_offs[n] = lo;
}

// ---------------------------------------------------------------------------
// Fuse W_a [9,64,96] and W_b [9,64,32] into W2 [576,128] row-major.
// Columns 0..95 pair with unweighted bins, 96..127 with weighted bins.
// ---------------------------------------------------------------------------
__global__ void build_w2_kernel(const float* __restrict__ Wa,
                                const float* __restrict__ Wb) {
    int i = blockIdx.x * blockDim.x + threadIdx.x;
    if (i >= KCDIM * CO) return;
    int kc = i / CO, o = i % CO;   // kc = k*64 + c
    g_W2[i] = (o < CA) ? __ldg(Wa + kc * CA + o)
                       : __ldg(Wb + kc * CB + (o - CA));
}

// ---------------------------------------------------------------------------
// Main fused kernel. One CTA handles MPTS=32 output points.
// smem: bins[2][32][576] (u then w halves) + imp_sum[32]   = 147,584 B
// Phase 1: warp w bins points {w, w+8, w+16, w+24} (exclusive ownership,
//          plain smem read-modify-write, no atomics).
// Phase 2: register-blocked GEMM [32 x 576] x [576 x 128]:
//          warp w -> points 4w..4w+3 ; lane -> channels 4*lane..4*lane+3.
// ---------------------------------------------------------------------------
extern __shared__ float s_dyn[];

__global__ __launch_bounds__(256, 1)
void sparse_conv_kernel(const float* __restrict__ feats,
                        const float* __restrict__ importance,
                        const float* __restrict__ b_a,
                        const float* __restrict__ b_b,
                        const int*   __restrict__ nbr,
                        const int*   __restrict__ kid,
                        float*       __restrict__ out) {
    float* s_bin = s_dyn;                       // [2 * MPTS * KCDIM]
    float* s_imp = s_dyn + 2 * MPTS * KCDIM;    // [MPTS]

    const int tid  = threadIdx.x;
    const int lane = tid & 31;
    const int w    = tid >> 5;                  // warp id 0..7
    const int n_base = blockIdx.x * MPTS;

    // ---- zero the bins --------------------------------------------------
    {
        float4* sz = reinterpret_cast<float4*>(s_bin);
        const int nv = (2 * MPTS * KCDIM) / 4;  // 9216
        #pragma unroll
        for (int i = tid; i < nv; i += 256) sz[i] = make_float4(0.f, 0.f, 0.f, 0.f);
    }
    __syncthreads();

    // ---- Phase 1: binning ------------------------------------------------
    for (int mi = w; mi < MPTS; mi += 8) {
        const int n  = n_base + mi;
        const int e0 = g_offs[n];
        const int e1 = g_offs[n + 1];
        float impacc = 0.f;
        float* bu = s_bin + mi * KCDIM;
        float* bw = s_bin + (MPTS + mi) * KCDIM;
        for (int e = e0; e < e1; e++) {
            const int   src = __ldg(nbr + e);
            const int   k   = __ldg(kid + e);
            const float imp = __ldg(importance + src);
            const float f0  = __ldg(feats + (size_t)src * CIN + lane);
            const float f1  = __ldg(feats + (size_t)src * CIN + 32 + lane);
            const int b = k * CIN + lane;
            bu[b]      += f0;
            bu[b + 32] += f1;
            bw[b]       = fmaf(f0, imp, bw[b]);
            bw[b + 32]  = fmaf(f1, imp, bw[b + 32]);
            impacc += imp;
        }
        if (lane == 0) s_imp[mi] = impacc;
    }
    __syncthreads();

    // ---- Phase 2: GEMM ----------------------------------------------------
    const int o0 = lane * 4;                            // channel base
    const float* A = s_bin + ((o0 >= CA) ? MPTS * KCDIM : 0) + (w * 4) * KCDIM;
    const float4* Wv = reinterpret_cast<const float4*>(g_W2) + lane;

    float acc[4][4];
    #pragma unroll
    for (int i = 0; i < 4; i++)
        #pragma unroll
        for (int j = 0; j < 4; j++) acc[i][j] = 0.f;

    #pragma unroll 4
    for (int kc = 0; kc < KCDIM; kc++) {
        const float4 wv = __ldg(&Wv[kc * (CO / 4)]);
        const float a0 = A[kc];
        const float a1 = A[KCDIM + kc];
        const float a2 = A[2 * KCDIM + kc];
        const float a3 = A[3 * KCDIM + kc];
        acc[0][0] = fmaf(a0, wv.x, acc[0][0]);
        acc[0][1] = fmaf(a0, wv.y, acc[0][1]);
        acc[0][2] = fmaf(a0, wv.z, acc[0][2]);
        acc[0][3] = fmaf(a0, wv.w, acc[0][3]);
        acc[1][0] = fmaf(a1, wv.x, acc[1][0]);
        acc[1][1] = fmaf(a1, wv.y, acc[1][1]);
        acc[1][2] = fmaf(a1, wv.z, acc[1][2]);
        acc[1][3] = fmaf(a1, wv.w, acc[1][3]);
        acc[2][0] = fmaf(a2, wv.x, acc[2][0]);
        acc[2][1] = fmaf(a2, wv.y, acc[2][1]);
        acc[2][2] = fmaf(a2, wv.z, acc[2][2]);
        acc[2][3] = fmaf(a2, wv.w, acc[2][3]);
        acc[3][0] = fmaf(a3, wv.x, acc[3][0]);
        acc[3][1] = fmaf(a3, wv.y, acc[3][1]);
        acc[3][2] = fmaf(a3, wv.z, acc[3][2]);
        acc[3][3] = fmaf(a3, wv.w, acc[3][3]);
    }

    // ---- Epilogue: bias, (normalize), relu, store -------------------------
    float bs0, bs1, bs2, bs3;
    if (o0 < CA) {
        bs0 = __ldg(b_a + o0);     bs1 = __ldg(b_a + o0 + 1);
        bs2 = __ldg(b_a + o0 + 2); bs3 = __ldg(b_a + o0 + 3);
    } else {
        bs0 = __ldg(b_b + o0 - CA);     bs1 = __ldg(b_b + o0 - CA + 1);
        bs2 = __ldg(b_b + o0 - CA + 2); bs3 = __ldg(b_b + o0 - CA + 3);
    }

    #pragma unroll
    for (int i = 0; i < 4; i++) {
        const int m = w * 4 + i;
        const int n = n_base + m;
        float scale = 1.f;
        if (o0 >= CA) scale = 1.f / fmaxf(s_imp[m], 1e-8f);
        float4 r;
        r.x = fmaxf(fmaf(acc[i][0], scale, bs0), 0.f);
        r.y = fmaxf(fmaf(acc[i][1], scale, bs1), 0.f);
        r.z = fmaxf(fmaf(acc[i][2], scale, bs2), 0.f);
        r.w = fmaxf(fmaf(acc[i][3], scale, bs3), 0.f);
        *reinterpret_cast<float4*>(out + (size_t)n * CO + o0) = r;
    }

    // imp_sum output (second tuple element), appended after feats1
    if (lane == 0) {
        #pragma unroll
        for (int i = 0; i < 4; i++) {
            const int m = w * 4 + i;
            out[(size_t)N_OUT * CO + (n_base + m)] = s_imp[m];
        }
    }
}

// ---------------------------------------------------------------------------
extern "C" void kernel_launch(void* const* d_in, const int* in_sizes, int n_in,
                              void* d_out, int out_size) {
    const float* feats      = (const float*)d_in[0];
    const float* importance = (const float*)d_in[1];
    const float* W_a        = (const float*)d_in[2];
    const float* b_a        = (const float*)d_in[3];
    const float* W_b        = (const float*)d_in[4];
    const float* b_b        = (const float*)d_in[5];
    const int*   nbr        = (const int*)d_in[6];
    const int*   kid        = (const int*)d_in[7];
    const int*   oid        = (const int*)d_in[8];
    float*       out        = (float*)d_out;

    build_offsets_kernel<<<(N_OUT + 256) / 256, 256>>>(oid);
    build_w2_kernel<<<(KCDIM * CO + 255) / 256, 256>>>(W_a, W_b);

    const int smem_bytes = (2 * MPTS * KCDIM + MPTS) * (int)sizeof(float); // 147,584 B
    cudaFuncSetAttribute(sparse_conv_kernel,
                         cudaFuncAttributeMaxDynamicSharedMemorySize, smem_bytes);
    sparse_conv_kernel<<<N_OUT / MPTS, 256, smem_bytes>>>(
        feats, importance, b_a, b_b, nbr, kid, out);
}

// round 3
// speedup vs baseline: 3.0031x; 3.0031x over previous
#include <cuda_runtime.h>
#include <cuda_bf16.h>
#include <cstdint>

// ---------------- problem constants ----------------
#define N_IN   200000
#define N_OUT  100000
#define NE     1600000
#define CIN    64
#define CO     128
#define KHALF  576             // u-bins (or w-bins) K dimension
#define MTILE  128
#define MPAD   100096          // 782 * 128
#define NTILES 782
#define KCH    64              // K elems per pipeline chunk
#define NCHUNK 27              // 3 passes x 9 chunks

// ---------------- device scratch (no allocs allowed) ----------------
__device__ int            g_offs[N_OUT + 1];
__device__ float          g_imp[N_OUT];
__device__ __nv_bfloat16  g_Bh[CO * KHALF];
__device__ __nv_bfloat16  g_Bl[CO * KHALF];
__device__ __nv_bfloat16  g_Auh[(size_t)MPAD * KHALF];  // padded rows stay zero (.bss)
__device__ __nv_bfloat16  g_Aul[(size_t)MPAD * KHALF];
__device__ __nv_bfloat16  g_Awh[(size_t)MPAD * KHALF];
__device__ __nv_bfloat16  g_Awl[(size_t)MPAD * KHALF];

// ---------------- helpers ----------------
__device__ __forceinline__ uint32_t smem_u32(const void* p) {
    uint32_t a;
    asm("{ .reg .u64 t; cvta.to.shared.u64 t, %1; cvt.u32.u64 %0, t; }"
        : "=r"(a) : "l"(p));
    return a;
}
__device__ __forceinline__ uint32_t sw128(uint32_t o) {
    return o ^ ((o >> 3) & 0x70);
}
__device__ __forceinline__ void cp16(uint32_t dst, const void* src) {
    asm volatile("cp.async.cg.shared.global [%0], [%1], 16;" :: "r"(dst), "l"(src));
}
#define CP_COMMIT asm volatile("cp.async.commit_group;" ::: "memory")

__device__ __forceinline__ void mma_bf16(float* c, uint32_t a0, uint32_t a1,
                                         uint32_t a2, uint32_t a3,
                                         uint32_t b0, uint32_t b1) {
    asm volatile(
        "mma.sync.aligned.m16n8k16.row.col.f32.bf16.bf16.f32 "
        "{%0,%1,%2,%3}, {%4,%5,%6,%7}, {%8,%9}, {%0,%1,%2,%3};"
        : "+f"(c[0]), "+f"(c[1]), "+f"(c[2]), "+f"(c[3])
        : "r"(a0), "r"(a1), "r"(a2), "r"(a3), "r"(b0), "r"(b1));
}

// ---------------------------------------------------------------------------
// Kernel 1: CSR offsets from sorted neighbors_out_index
// ---------------------------------------------------------------------------
__global__ void build_offsets_kernel(const int* __restrict__ out_idx) {
    int n = blockIdx.x * blockDim.x + threadIdx.x;
    if (n > N_OUT) return;
    int lo = 0, hi = NE;
    while (lo < hi) {
        int mid = (lo + hi) >> 1;
        if (__ldg(out_idx + mid) < n) lo = mid + 1; else hi = mid;
    }
    g_offs[n] = lo;
}

// ---------------------------------------------------------------------------
// Kernel 2: compressed weight matrix [128][576], bf16 hi/lo split
//   row o<96 : Wa[k][o]  (k = kk*64+c over u-bins)
//   row o>=96: Wb[k][o-96]  (over w-bins)
// ---------------------------------------------------------------------------
__global__ void build_w_kernel(const float* __restrict__ Wa,
                               const float* __restrict__ Wb) {
    int i = blockIdx.x * blockDim.x + threadIdx.x;
    if (i >= CO * KHALF) return;
    int o = i / KHALF, k = i % KHALF;
    float v = (o < 96) ? __ldg(Wa + k * 96 + o) : __ldg(Wb + k * 32 + (o - 96));
    __nv_bfloat16 h = __float2bfloat16(v);
    g_Bh[i] = h;
    g_Bl[i] = __float2bfloat16(v - __bfloat162float(h));
}

// ---------------------------------------------------------------------------
// Kernel 3: binning. One warp per output point; fp32 bins in smem;
// bf16 hi/lo split written to global staging (u and w halves separately).
// ---------------------------------------------------------------------------
__global__ __launch_bounds__(256)
void bin_kernel(const float* __restrict__ feats,
                const float* __restrict__ importance,
                const int*   __restrict__ nbr,
                const int*   __restrict__ kid,
                float*       __restrict__ out) {
    __shared__ float sb[8][1152];
    const int lane = threadIdx.x & 31;
    const int w    = threadIdx.x >> 5;
    const int n    = blockIdx.x * 8 + w;     // grid sized exactly

    float* b = sb[w];
    float4* bz = reinterpret_cast<float4*>(b);
    #pragma unroll
    for (int i = lane; i < 1152 / 4; i += 32) bz[i] = make_float4(0.f, 0.f, 0.f, 0.f);
    __syncwarp();

    const int e0 = g_offs[n], e1 = g_offs[n + 1];
    float impacc = 0.f;
    for (int e = e0; e < e1; e++) {
        const int   src = __ldg(nbr + e);
        const int   k   = __ldg(kid + e);
        const float im  = __ldg(importance + src);
        const float f0  = __ldg(feats + (size_t)src * CIN + lane);
        const float f1  = __ldg(feats + (size_t)src * CIN + 32 + lane);
        const int o = k * CIN + lane;
        b[o]       += f0;
        b[o + 32]  += f1;
        b[576 + o]      = fmaf(f0, im, b[576 + o]);
        b[576 + o + 32] = fmaf(f1, im, b[576 + o + 32]);
        impacc += im;
    }
    __syncwarp();

    const size_t base = (size_t)n * KHALF;
    #pragma unroll
    for (int j = 0; j < KHALF; j += 64) {
        const int kc = j + 2 * lane;
        // u half
        {
            float2 v = *reinterpret_cast<float2*>(b + kc);
            __nv_bfloat162 hh, ll;
            hh.x = __float2bfloat16(v.x); hh.y = __float2bfloat16(v.y);
            ll.x = __float2bfloat16(v.x - __bfloat162float(hh.x));
            ll.y = __float2bfloat16(v.y - __bfloat162float(hh.y));
            *reinterpret_cast<__nv_bfloat162*>(g_Auh + base + kc) = hh;
            *reinterpret_cast<__nv_bfloat162*>(g_Aul + base + kc) = ll;
        }
        // w half
        {
            float2 v = *reinterpret_cast<float2*>(b + 576 + kc);
            __nv_bfloat162 hh, ll;
            hh.x = __float2bfloat16(v.x); hh.y = __float2bfloat16(v.y);
            ll.x = __float2bfloat16(v.x - __bfloat162float(hh.x));
            ll.y = __float2bfloat16(v.y - __bfloat162float(hh.y));
            *reinterpret_cast<__nv_bfloat162*>(g_Awh + base + kc) = hh;
            *reinterpret_cast<__nv_bfloat162*>(g_Awl + base + kc) = ll;
        }
    }
    if (lane == 0) {
        g_imp[n] = impacc;
        out[(size_t)N_OUT * CO + n] = impacc;   // imp_sum output
    }
}

// ---------------------------------------------------------------------------
// Kernel 4: HMMA GEMM. CTA tile 128(M) x 128(N); K = 3 passes x 576.
// smem stages (x3): Au[128][64] | Aw[128][64] | B[128][64]  = 48KB each,
// all bf16 rows of 128B with SW128 swizzle (conflict-free 4B fragment LDS).
// Warps: 2(M64) x 4(N32); n-tiles 0..2 use Au, n-tile 3 uses Aw.
// ---------------------------------------------------------------------------
extern __shared__ __align__(1024) char gsm[];

__device__ __forceinline__ void stage_loads(uint32_t st, size_t mtile, int c, int tid) {
    const int pass = c / 9, k0 = (c % 9) * KCH;
    const __nv_bfloat16* au = (pass < 2) ? g_Auh : g_Aul;
    const __nv_bfloat16* aw = (pass < 2) ? g_Awh : g_Awl;
    const __nv_bfloat16* bb = (pass == 1) ? g_Bl : g_Bh;
    #pragma unroll
    for (int q = 0; q < 4; q++) {
        const int idx = q * 256 + tid;
        const int row = idx >> 3, ch = idx & 7;
        const uint32_t sw = sw128(row * 128 + ch * 16);
        const size_t gof = k0 + ch * 8;
        cp16(st + sw,         au + (mtile + row) * KHALF + gof);
        cp16(st + 16384 + sw, aw + (mtile + row) * KHALF + gof);
        cp16(st + 32768 + sw, bb + (size_t)row * KHALF + gof);
    }
    CP_COMMIT;
}

__global__ __launch_bounds__(256, 1)
void gemm_kernel(const float* __restrict__ b_a,
                 const float* __restrict__ b_b,
                 float*       __restrict__ out) {
    const int tid = threadIdx.x, lane = tid & 31, wid = tid >> 5;
    const int w_m = wid & 1, w_n = wid >> 1;          // M64 row, N32 col tile
    const int g = lane >> 2, tig = lane & 3;
    const size_t mtile = (size_t)blockIdx.x * MTILE;
    const uint32_t sbase = smem_u32(gsm);

    float acc[4][4][4];
    #pragma unroll
    for (int i = 0; i < 4; i++)
        #pragma unroll
        for (int j = 0; j < 4; j++)
            #pragma unroll
            for (int q = 0; q < 4; q++) acc[i][j][q] = 0.f;

    // prologue: stages 0,1
    stage_loads(sbase,         mtile, 0, tid);
    stage_loads(sbase + 49152, mtile, 1, tid);

    for (int c = 0; c < NCHUNK; c++) {
        if (c == NCHUNK - 1) asm volatile("cp.async.wait_group 0;" ::: "memory");
        else                 asm volatile("cp.async.wait_group 1;" ::: "memory");
        __syncthreads();
        if (c + 2 < NCHUNK)
            stage_loads(sbase + ((c + 2) % 3) * 49152, mtile, c + 2, tid);

        const char* base = gsm + (c % 3) * 49152;
        const char* sA = base + ((w_n < 3) ? 0 : 16384);
        const char* sB = base + 32768;

        #pragma unroll
        for (int ks = 0; ks < 4; ks++) {
            const int cb = ks * 32 + tig * 4;        // byte col of k-pair
            uint32_t bf[4][2];
            #pragma unroll
            for (int nf = 0; nf < 4; nf++) {
                const int r = w_n * 32 + nf * 8 + g;
                bf[nf][0] = *(const uint32_t*)(sB + sw128(r * 128 + cb));
                bf[nf][1] = *(const uint32_t*)(sB + sw128(r * 128 + cb + 16));
            }
            #pragma unroll
            for (int mf = 0; mf < 4; mf++) {
                const int r = w_m * 64 + mf * 16 + g;
                const uint32_t a0 = *(const uint32_t*)(sA + sw128(r * 128 + cb));
                const uint32_t a1 = *(const uint32_t*)(sA + sw128((r + 8) * 128 + cb));
                const uint32_t a2 = *(const uint32_t*)(sA + sw128(r * 128 + cb + 16));
                const uint32_t a3 = *(const uint32_t*)(sA + sw128((r + 8) * 128 + cb + 16));
                #pragma unroll
                for (int nf = 0; nf < 4; nf++)
                    mma_bf16(acc[mf][nf], a0, a1, a2, a3, bf[nf][0], bf[nf][1]);
            }
        }
    }

    // ---- epilogue: bias / normalize / relu / store ----
    float bias[4][2];
    #pragma unroll
    for (int nf = 0; nf < 4; nf++) {
        const int col = w_n * 32 + nf * 8 + 2 * tig;
        bias[nf][0] = (col < 96) ? __ldg(b_a + col)     : __ldg(b_b + col - 96);
        bias[nf][1] = (col < 96) ? __ldg(b_a + col + 1) : __ldg(b_b + col - 95);
    }

    #pragma unroll
    for (int mf = 0; mf < 4; mf++) {
        #pragma unroll
        for (int half = 0; half < 2; half++) {
            const int n = (int)mtile + w_m * 64 + mf * 16 + g + half * 8;
            if (n >= N_OUT) continue;
            float inv = 1.f;
            if (w_n == 3) inv = 1.f / fmaxf(__ldg(g_imp + n), 1e-8f);
            #pragma unroll
            for (int nf = 0; nf < 4; nf++) {
                const int col = w_n * 32 + nf * 8 + 2 * tig;
                float v0 = acc[mf][nf][half * 2 + 0];
                float v1 = acc[mf][nf][half * 2 + 1];
                float2 r;
                r.x = fmaxf(fmaf(v0, inv, bias[nf][0]), 0.f);
                r.y = fmaxf(fmaf(v1, inv, bias[nf][1]), 0.f);
                *reinterpret_cast<float2*>(out + (size_t)n * CO + col) = r;
            }
        }
    }
}

// ---------------------------------------------------------------------------
extern "C" void kernel_launch(void* const* d_in, const int* in_sizes, int n_in,
                              void* d_out, int out_size) {
    const float* feats      = (const float*)d_in[0];
    const float* importance = (const float*)d_in[1];
    const float* W_a        = (const float*)d_in[2];
    const float* b_a        = (const float*)d_in[3];
    const float* W_b        = (const float*)d_in[4];
    const float* b_b        = (const float*)d_in[5];
    const int*   nbr        = (const int*)d_in[6];
    const int*   kid        = (const int*)d_in[7];
    const int*   oid        = (const int*)d_in[8];
    float*       out        = (float*)d_out;

    build_offsets_kernel<<<(N_OUT + 256) / 256, 256>>>(oid);
    build_w_kernel<<<(CO * KHALF + 255) / 256, 256>>>(W_a, W_b);
    bin_kernel<<<N_OUT / 8, 256>>>(feats, importance, nbr, kid, out);

    const int smem_bytes = 3 * 49152;   // 147,456 B
    cudaFuncSetAttribute(gemm_kernel,
                         cudaFuncAttributeMaxDynamicSharedMemorySize, smem_bytes);
    gemm_kernel<<<NTILES, 256, smem_bytes>>>(b_a, b_b, out);
}

// round 4
// speedup vs baseline: 3.3675x; 1.1213x over previous
#include <cuda_runtime.h>
#include <cuda_bf16.h>
#include <cstdint>

// ---------------- problem constants ----------------
#define N_IN   200000
#define N_OUT  100000
#define NE     1600000
#define CIN    64
#define CO     128
#define KHALF  576
#define MTILE  128
#define MPAD   100096          // 782 * 128
#define NTILES 782
#define KCH    32              // K elems per pipeline chunk
#define NCHUNK 18              // 576 / 32

#define ASZ    ((size_t)MPAD * KHALF)
#define BSZ    ((size_t)CO * KHALF)

// ---------------- device scratch (no allocs allowed) ----------------
__device__ int            g_offs[N_OUT + 1];
__device__ float          g_imp[N_OUT];
// A arrays: 0=Auh 1=Aul 2=Awh 3=Awl ; padded rows stay zero (.bss)
__device__ __nv_bfloat16  g_A[4][ASZ];
// B arrays: 0=Bh 1=Bl
__device__ __nv_bfloat16  g_B[2][BSZ];

// ---------------- helpers ----------------
__device__ __forceinline__ uint32_t smem_u32(const void* p) {
    uint32_t a;
    asm("{ .reg .u64 t; cvta.to.shared.u64 t, %1; cvt.u32.u64 %0, t; }"
        : "=r"(a) : "l"(p));
    return a;
}
__device__ __forceinline__ uint32_t sw64(uint32_t o) {   // 64B-row swizzle
    return o ^ ((o >> 3) & 0x30);
}
__device__ __forceinline__ void cp16(uint32_t dst, const void* src) {
    asm volatile("cp.async.cg.shared.global [%0], [%1], 16;" :: "r"(dst), "l"(src));
}
#define CP_COMMIT asm volatile("cp.async.commit_group;" ::: "memory")

__device__ __forceinline__ void ldm4(uint32_t& r0, uint32_t& r1,
                                     uint32_t& r2, uint32_t& r3, uint32_t a) {
    asm volatile("ldmatrix.sync.aligned.m8n8.x4.shared.b16 {%0,%1,%2,%3}, [%4];"
                 : "=r"(r0), "=r"(r1), "=r"(r2), "=r"(r3) : "r"(a));
}
__device__ __forceinline__ void mma_bf16(float* c, const uint32_t* a,
                                         uint32_t b0, uint32_t b1) {
    asm volatile(
        "mma.sync.aligned.m16n8k16.row.col.f32.bf16.bf16.f32 "
        "{%0,%1,%2,%3}, {%4,%5,%6,%7}, {%8,%9}, {%0,%1,%2,%3};"
        : "+f"(c[0]), "+f"(c[1]), "+f"(c[2]), "+f"(c[3])
        : "r"(a[0]), "r"(a[1]), "r"(a[2]), "r"(a[3]), "r"(b0), "r"(b1));
}

// ---------------------------------------------------------------------------
// Kernel 1: CSR offsets via adjacent-diff over sorted neighbors_out_index
// ---------------------------------------------------------------------------
__global__ void build_offsets_kernel(const int* __restrict__ out_idx) {
    int e = blockIdx.x * blockDim.x + threadIdx.x;
    if (e >= NE) return;
    int b = __ldg(out_idx + e);
    int a = (e == 0) ? -1 : __ldg(out_idx + e - 1);
    for (int n = a + 1; n <= b; n++) g_offs[n] = e;
    if (e == NE - 1)
        for (int n = b + 1; n <= N_OUT; n++) g_offs[n] = NE;
}

// ---------------------------------------------------------------------------
// Kernel 2: compressed weights [128][576] bf16 hi/lo
// ---------------------------------------------------------------------------
__global__ void build_w_kernel(const float* __restrict__ Wa,
                               const float* __restrict__ Wb) {
    int i = blockIdx.x * blockDim.x + threadIdx.x;
    if (i >= CO * KHALF) return;
    int o = i / KHALF, k = i % KHALF;
    float v = (o < 96) ? __ldg(Wa + k * 96 + o) : __ldg(Wb + k * 32 + (o - 96));
    __nv_bfloat16 h = __float2bfloat16(v);
    g_B[0][i] = h;
    g_B[1][i] = __float2bfloat16(v - __bfloat162float(h));
}

// ---------------------------------------------------------------------------
// Kernel 3: binning. One warp per output point; float2 gather + smem RMW.
// ---------------------------------------------------------------------------
__global__ __launch_bounds__(256)
void bin_kernel(const float* __restrict__ feats,
                const float* __restrict__ importance,
                const int*   __restrict__ nbr,
                const int*   __restrict__ kid,
                float*       __restrict__ out) {
    __shared__ float sb[8][1152];
    const int lane = threadIdx.x & 31;
    const int w    = threadIdx.x >> 5;
    const int n    = blockIdx.x * 8 + w;

    float*  b  = sb[w];
    float2* b2 = reinterpret_cast<float2*>(b);
    float4* bz = reinterpret_cast<float4*>(b);
    #pragma unroll
    for (int i = lane; i < 1152 / 4; i += 32) bz[i] = make_float4(0.f, 0.f, 0.f, 0.f);
    __syncwarp();

    const int e0 = g_offs[n], e1 = g_offs[n + 1];
    float impacc = 0.f;
    for (int e = e0; e < e1; e++) {
        const int    src = __ldg(nbr + e);
        const int    k   = __ldg(kid + e);
        const float  im  = __ldg(importance + src);
        const float2 f   = *reinterpret_cast<const float2*>(
                               feats + (size_t)src * CIN + 2 * lane);
        const int o2 = k * 32 + lane;
        float2 bu = b2[o2];
        bu.x += f.x; bu.y += f.y;
        b2[o2] = bu;
        float2 bw = b2[288 + o2];
        bw.x = fmaf(f.x, im, bw.x); bw.y = fmaf(f.y, im, bw.y);
        b2[288 + o2] = bw;
        impacc += im;
    }
    __syncwarp();

    const size_t base = (size_t)n * KHALF;
    #pragma unroll
    for (int j = 0; j < KHALF; j += 64) {
        const int kc = j + 2 * lane;
        {   // u half -> g_A[0]/g_A[1]
            float2 v = *reinterpret_cast<float2*>(b + kc);
            __nv_bfloat162 hh, ll;
            hh.x = __float2bfloat16(v.x); hh.y = __float2bfloat16(v.y);
            ll.x = __float2bfloat16(v.x - __bfloat162float(hh.x));
            ll.y = __float2bfloat16(v.y - __bfloat162float(hh.y));
            *reinterpret_cast<__nv_bfloat162*>(&g_A[0][base + kc]) = hh;
            *reinterpret_cast<__nv_bfloat162*>(&g_A[1][base + kc]) = ll;
        }
        {   // w half -> g_A[2]/g_A[3]
            float2 v = *reinterpret_cast<float2*>(b + 576 + kc);
            __nv_bfloat162 hh, ll;
            hh.x = __float2bfloat16(v.x); hh.y = __float2bfloat16(v.y);
            ll.x = __float2bfloat16(v.x - __bfloat162float(hh.x));
            ll.y = __float2bfloat16(v.y - __bfloat162float(hh.y));
            *reinterpret_cast<__nv_bfloat162*>(&g_A[2][base + kc]) = hh;
            *reinterpret_cast<__nv_bfloat162*>(&g_A[3][base + kc]) = ll;
        }
    }
    if (lane == 0) {
        g_imp[n] = impacc;
        out[(size_t)N_OUT * CO + n] = impacc;   // imp_sum output
    }
}

// ---------------------------------------------------------------------------
// Kernel 4: HMMA GEMM with ldmatrix fragments + chunk-local 3-pass.
// Stage (48KB): [Auh 8K][Aul 8K][Awh 8K][Awl 8K][Bh 8K][Bl 8K], rows 64B SW64.
// 2 stages, 2 CTAs/SM. Warps: 2(M64) x 4(N32); w_n<3 -> Au, w_n==3 -> Aw.
// ---------------------------------------------------------------------------
#define STAGE  49152
extern __shared__ char gsm[];

__global__ __launch_bounds__(256, 2)
void gemm_kernel(const float* __restrict__ b_a,
                 const float* __restrict__ b_b,
                 float*       __restrict__ out) {
    const int tid = threadIdx.x, lane = tid & 31, wid = tid >> 5;
    const int w_m = wid & 1, w_n = wid >> 1;
    const int g = lane >> 2, tig = lane & 3;
    const size_t mtile = (size_t)blockIdx.x * MTILE;
    const uint32_t sbase = smem_u32(gsm);

    // per-thread cp.async geometry (2 slots of 512 total 16B copies / array)
    int   aIdx[2], bIdx[2];
    uint32_t dOff[2];
    #pragma unroll
    for (int q = 0; q < 2; q++) {
        const int idx = q * 256 + tid;      // 0..511
        const int row = idx >> 2, c = idx & 3;
        aIdx[q] = (int)((mtile + row) * KHALF + c * 8);
        bIdx[q] = row * KHALF + c * 8;
        dOff[q] = sw64(row * 64 + c * 16);
    }

    // ldmatrix per-lane base offsets
    const uint32_t aOffB = (uint32_t)(w_m * 64 + (lane & 15)) * 64
                         + ((lane >> 4) & 1) * 16;
    const uint32_t bOffB = (uint32_t)(w_n * 32 + (lane & 7) + ((lane >> 4) & 1) * 8) * 64
                         + ((lane >> 3) & 1) * 16;
    const uint32_t ahSel = (w_n < 3) ? 0u : 16384u;   // Auh vs Awh

    float acc[4][4][4];
    #pragma unroll
    for (int i = 0; i < 4; i++)
        #pragma unroll
        for (int j = 0; j < 4; j++)
            #pragma unroll
            for (int q = 0; q < 4; q++) acc[i][j][q] = 0.f;

    // issue loads for chunk c into stage st
    auto issue = [&](int c, uint32_t st) {
        const int k0 = c * KCH;
        #pragma unroll
        for (int q = 0; q < 2; q++) {
            #pragma unroll
            for (int arr = 0; arr < 4; arr++)
                cp16(st + arr * 8192 + dOff[q], &g_A[arr][0] + aIdx[q] + k0);
            #pragma unroll
            for (int arr = 0; arr < 2; arr++)
                cp16(st + 32768 + arr * 8192 + dOff[q], &g_B[arr][0] + bIdx[q] + k0);
        }
        CP_COMMIT;
    };

    issue(0, sbase);

    #pragma unroll 2
    for (int c = 0; c < NCHUNK; c++) {
        if (c + 1 < NCHUNK) {
            issue(c + 1, sbase + ((c + 1) & 1) * STAGE);
            asm volatile("cp.async.wait_group 1;" ::: "memory");
        } else {
            asm volatile("cp.async.wait_group 0;" ::: "memory");
        }
        __syncthreads();

        const uint32_t st  = sbase + (c & 1) * STAGE;
        const uint32_t sAh = st + ahSel;
        const uint32_t sAl = sAh + 8192;
        const uint32_t sBh = st + 32768;
        const uint32_t sBl = st + 40960;

        #pragma unroll
        for (int ks = 0; ks < 2; ks++) {
            uint32_t bh[8], bl[8];
            ldm4(bh[0], bh[1], bh[2], bh[3], sBh + sw64(bOffB + ks * 32));
            ldm4(bh[4], bh[5], bh[6], bh[7], sBh + sw64(bOffB + 1024 + ks * 32));
            ldm4(bl[0], bl[1], bl[2], bl[3], sBl + sw64(bOffB + ks * 32));
            ldm4(bl[4], bl[5], bl[6], bl[7], sBl + sw64(bOffB + 1024 + ks * 32));
            #pragma unroll
            for (int mf = 0; mf < 4; mf++) {
                const uint32_t ao = sw64(aOffB + mf * 1024 + ks * 32);
                uint32_t ah[4], al[4];
                ldm4(ah[0], ah[1], ah[2], ah[3], sAh + ao);
                ldm4(al[0], al[1], al[2], al[3], sAl + ao);
                #pragma unroll
                for (int nf = 0; nf < 4; nf++) {
                    mma_bf16(acc[mf][nf], ah, bh[2 * nf], bh[2 * nf + 1]);
                    mma_bf16(acc[mf][nf], ah, bl[2 * nf], bl[2 * nf + 1]);
                    mma_bf16(acc[mf][nf], al, bh[2 * nf], bh[2 * nf + 1]);
                }
            }
        }
        __syncthreads();
    }

    // ---- epilogue: bias / normalize / relu / store ----
    float bias[4][2];
    #pragma unroll
    for (int nf = 0; nf < 4; nf++) {
        const int col = w_n * 32 + nf * 8 + 2 * tig;
        bias[nf][0] = (col < 96) ? __ldg(b_a + col)     : __ldg(b_b + col - 96);
        bias[nf][1] = (col < 96) ? __ldg(b_a + col + 1) : __ldg(b_b + col - 95);
    }

    #pragma unroll
    for (int mf = 0; mf < 4; mf++) {
        #pragma unroll
        for (int half = 0; half < 2; half++) {
            const int n = (int)mtile + w_m * 64 + mf * 16 + g + half * 8;
            if (n >= N_OUT) continue;
            float inv = 1.f;
            if (w_n == 3) inv = 1.f / fmaxf(__ldg(g_imp + n), 1e-8f);
            #pragma unroll
            for (int nf = 0; nf < 4; nf++) {
                const int col = w_n * 32 + nf * 8 + 2 * tig;
                float2 r;
                r.x = fmaxf(fmaf(acc[mf][nf][half * 2 + 0], inv, bias[nf][0]), 0.f);
                r.y = fmaxf(fmaf(acc[mf][nf][half * 2 + 1], inv, bias[nf][1]), 0.f);
                *reinterpret_cast<float2*>(out + (size_t)n * CO + col) = r;
            }
        }
    }
}

// ---------------------------------------------------------------------------
extern "C" void kernel_launch(void* const* d_in, const int* in_sizes, int n_in,
                              void* d_out, int out_size) {
    const float* feats      = (const float*)d_in[0];
    const float* importance = (const float*)d_in[1];
    const float* W_a        = (const float*)d_in[2];
    const float* b_a        = (const float*)d_in[3];
    const float* W_b        = (const float*)d_in[4];
    const float* b_b        = (const float*)d_in[5];
    const int*   nbr        = (const int*)d_in[6];
    const int*   kid        = (const int*)d_in[7];
    const int*   oid        = (const int*)d_in[8];
    float*       out        = (float*)d_out;

    build_offsets_kernel<<<(NE + 255) / 256, 256>>>(oid);
    build_w_kernel<<<(CO * KHALF + 255) / 256, 256>>>(W_a, W_b);
    bin_kernel<<<N_OUT / 8, 256>>>(feats, importance, nbr, kid, out);

    const int smem_bytes = 2 * STAGE;   // 98,304 B
    cudaFuncSetAttribute(gemm_kernel,
                         cudaFuncAttributeMaxDynamicSharedMemorySize, smem_bytes);
    gemm_kernel<<<NTILES, 256, smem_bytes>>>(b_a, b_b, out);
}